// round 1
// baseline (speedup 1.0000x reference)
#include <cuda_runtime.h>
#include <math.h>

// Problem dims (fixed for this dataset entry)
#define H_DIM 4096
#define I_DIM 11008
#define NTOK  4096   // B*L = 2*2048

#define BM 128
#define BN 128
#define BK 8
#define NTHREADS 256

// Device scratch (allocation-free rule: __device__ globals)
__device__ float g_h[(size_t)NTOK * I_DIM];   // compacted intermediate [m, I]
__device__ int   g_idx[NTOK];                 // compacted token indices
__device__ int   g_count;                     // number of active tokens

// ---------------------------------------------------------------------------
// Deterministic compaction: scan over 4096 mask entries, single block.
// ---------------------------------------------------------------------------
__global__ void compact_kernel(const int* __restrict__ mask) {
    __shared__ int warp_sums[32];
    const int tid  = threadIdx.x;          // 1024 threads, 4 tokens each
    const int lane = tid & 31;
    const int warp = tid >> 5;

    int flags[4];
    int cnt = 0;
#pragma unroll
    for (int j = 0; j < 4; ++j) {
        int t = tid * 4 + j;
        int f = (mask[t] != 0) ? 1 : 0;
        flags[j] = f;
        cnt += f;
    }
    // warp inclusive scan of cnt
    int v = cnt;
#pragma unroll
    for (int o = 1; o < 32; o <<= 1) {
        int n = __shfl_up_sync(0xFFFFFFFFu, v, o);
        if (lane >= o) v += n;
    }
    if (lane == 31) warp_sums[warp] = v;
    __syncthreads();
    if (warp == 0) {
        int s = warp_sums[lane];
#pragma unroll
        for (int o = 1; o < 32; o <<= 1) {
            int n = __shfl_up_sync(0xFFFFFFFFu, s, o);
            if (lane >= o) s += n;
        }
        warp_sums[lane] = s;
    }
    __syncthreads();
    int base = v - cnt + (warp > 0 ? warp_sums[warp - 1] : 0);
#pragma unroll
    for (int j = 0; j < 4; ++j) {
        if (flags[j]) g_idx[base++] = tid * 4 + j;
    }
    if (tid == 1023) g_count = base;  // == grand total
}

// ---------------------------------------------------------------------------
// Zero the output (masked rows stay zero; active rows overwritten by scatter)
// ---------------------------------------------------------------------------
__global__ void zero_out_kernel(float4* __restrict__ out, int n4) {
    int i = blockIdx.x * blockDim.x + threadIdx.x;
    if (i < n4) out[i] = make_float4(0.f, 0.f, 0.f, 0.f);
}

// ---------------------------------------------------------------------------
// NT GEMM: C[m,n] = dot(A[m, 0..K), B[n, 0..K))   (both operands K-major)
// MODE 0: A = hidden gathered via g_idx ; epilogue: g_h = silu(acc)
// MODE 1: A = hidden gathered via g_idx ; epilogue: g_h *= acc
// MODE 2: A = g_h (already compacted)   ; epilogue: out[g_idx[m]] = acc
// Classic 128x128x8 double-buffered SGEMM, 8x8 microtile, 256 threads.
// ---------------------------------------------------------------------------
template <int MODE>
__global__ __launch_bounds__(NTHREADS, 2)
void gemm_kernel(const float* __restrict__ A,
                 const float* __restrict__ B,
                 float* __restrict__ C,
                 int K)
{
    const int Mc = g_count;
    if ((int)(blockIdx.y * BM) >= Mc) return;

    __shared__ float As[2][BK][BM];
    __shared__ float Bs[2][BK][BN];

    const int tid   = threadIdx.x;
    const int l_row = tid >> 1;            // 0..127 (shared by A and B loaders)
    const int l_col = (tid & 1) << 2;      // 0 or 4

    // Resolve A source row pointer once
    const float* Abase = (MODE == 2) ? g_h : A;
    const float* Aptr;
    {
        int gm = blockIdx.y * BM + l_row;
        if (MODE == 2) {
            Aptr = Abase + (size_t)gm * K + l_col;      // g_h rows are zero-padded
        } else {
            Aptr = (gm < Mc) ? (Abase + (size_t)g_idx[gm] * K + l_col) : nullptr;
        }
    }
    const float* Bptr = B + (size_t)(blockIdx.x * BN + l_row) * K + l_col;

    // Prologue: tile 0 -> buffer 0
    float4 a_reg = Aptr ? *(const float4*)(Aptr) : make_float4(0.f, 0.f, 0.f, 0.f);
    float4 b_reg = *(const float4*)(Bptr);
    As[0][l_col + 0][l_row] = a_reg.x;
    As[0][l_col + 1][l_row] = a_reg.y;
    As[0][l_col + 2][l_row] = a_reg.z;
    As[0][l_col + 3][l_row] = a_reg.w;
    Bs[0][l_col + 0][l_row] = b_reg.x;
    Bs[0][l_col + 1][l_row] = b_reg.y;
    Bs[0][l_col + 2][l_row] = b_reg.z;
    Bs[0][l_col + 3][l_row] = b_reg.w;
    __syncthreads();

    const int ty = tid >> 4;   // 0..15 -> M rows ty*8..+7
    const int tx = tid & 15;   // 0..15 -> N cols tx*8..+7

    float acc[8][8];
#pragma unroll
    for (int i = 0; i < 8; ++i)
#pragma unroll
        for (int j = 0; j < 8; ++j) acc[i][j] = 0.f;

    const int nk = K / BK;
    for (int t = 0; t < nk; ++t) {
        const int buf = t & 1;
        if (t + 1 < nk) {
            const int k0 = (t + 1) * BK;
            a_reg = Aptr ? *(const float4*)(Aptr + k0) : make_float4(0.f, 0.f, 0.f, 0.f);
            b_reg = *(const float4*)(Bptr + k0);
        }
#pragma unroll
        for (int k = 0; k < BK; ++k) {
            float4 a0 = *(const float4*)&As[buf][k][ty * 8];
            float4 a1 = *(const float4*)&As[buf][k][ty * 8 + 4];
            float4 b0 = *(const float4*)&Bs[buf][k][tx * 8];
            float4 b1 = *(const float4*)&Bs[buf][k][tx * 8 + 4];
            float ar[8] = {a0.x, a0.y, a0.z, a0.w, a1.x, a1.y, a1.z, a1.w};
            float br[8] = {b0.x, b0.y, b0.z, b0.w, b1.x, b1.y, b1.z, b1.w};
#pragma unroll
            for (int i = 0; i < 8; ++i)
#pragma unroll
                for (int j = 0; j < 8; ++j)
                    acc[i][j] = fmaf(ar[i], br[j], acc[i][j]);
        }
        if (t + 1 < nk) {
            const int nb = buf ^ 1;
            As[nb][l_col + 0][l_row] = a_reg.x;
            As[nb][l_col + 1][l_row] = a_reg.y;
            As[nb][l_col + 2][l_row] = a_reg.z;
            As[nb][l_col + 3][l_row] = a_reg.w;
            Bs[nb][l_col + 0][l_row] = b_reg.x;
            Bs[nb][l_col + 1][l_row] = b_reg.y;
            Bs[nb][l_col + 2][l_row] = b_reg.z;
            Bs[nb][l_col + 3][l_row] = b_reg.w;
        }
        __syncthreads();
    }

    // Epilogue
    const int gm0 = blockIdx.y * BM + ty * 8;
    const int gn0 = blockIdx.x * BN + tx * 8;

    if (MODE == 0) {
        // g_h = silu(acc); padding rows produce silu(0)=0, safe to store.
#pragma unroll
        for (int i = 0; i < 8; ++i) {
            float* row = g_h + (size_t)(gm0 + i) * I_DIM + gn0;
            float4 v0, v1;
            float s;
            s = acc[i][0]; v0.x = s / (1.f + expf(-s));
            s = acc[i][1]; v0.y = s / (1.f + expf(-s));
            s = acc[i][2]; v0.z = s / (1.f + expf(-s));
            s = acc[i][3]; v0.w = s / (1.f + expf(-s));
            s = acc[i][4]; v1.x = s / (1.f + expf(-s));
            s = acc[i][5]; v1.y = s / (1.f + expf(-s));
            s = acc[i][6]; v1.z = s / (1.f + expf(-s));
            s = acc[i][7]; v1.w = s / (1.f + expf(-s));
            *(float4*)(row)     = v0;
            *(float4*)(row + 4) = v1;
        }
    } else if (MODE == 1) {
        // g_h *= acc (up projection)
#pragma unroll
        for (int i = 0; i < 8; ++i) {
            float* row = g_h + (size_t)(gm0 + i) * I_DIM + gn0;
            float4 h0 = *(float4*)(row);
            float4 h1 = *(float4*)(row + 4);
            h0.x *= acc[i][0]; h0.y *= acc[i][1]; h0.z *= acc[i][2]; h0.w *= acc[i][3];
            h1.x *= acc[i][4]; h1.y *= acc[i][5]; h1.z *= acc[i][6]; h1.w *= acc[i][7];
            *(float4*)(row)     = h0;
            *(float4*)(row + 4) = h1;
        }
    } else {
        // scatter to output rows via g_idx
#pragma unroll
        for (int i = 0; i < 8; ++i) {
            int gm = gm0 + i;
            if (gm < Mc) {
                int tok = g_idx[gm];
                float* row = C + (size_t)tok * H_DIM + gn0;
                float4 v0 = make_float4(acc[i][0], acc[i][1], acc[i][2], acc[i][3]);
                float4 v1 = make_float4(acc[i][4], acc[i][5], acc[i][6], acc[i][7]);
                *(float4*)(row)     = v0;
                *(float4*)(row + 4) = v1;
            }
        }
    }
}

// ---------------------------------------------------------------------------
extern "C" void kernel_launch(void* const* d_in, const int* in_sizes, int n_in,
                              void* d_out, int out_size)
{
    const float* hidden = (const float*)d_in[0];  // [2,2048,4096]
    const float* w_up   = (const float*)d_in[1];  // [11008,4096]
    const float* w_gate = (const float*)d_in[2];  // [11008,4096]
    const float* w_down = (const float*)d_in[3];  // [4096,11008]
    const int*   mask   = (const int*)d_in[4];    // [2,2048]
    float* out = (float*)d_out;                   // [2,2048,4096] fp32

    compact_kernel<<<1, 1024>>>(mask);

    const int n4 = (NTOK * H_DIM) / 4;
    zero_out_kernel<<<(n4 + 255) / 256, 256>>>((float4*)out, n4);

    dim3 blk(NTHREADS);
    dim3 grid_ug(I_DIM / BN, NTOK / BM);   // 86 x 32 (half exit early)
    dim3 grid_dn(H_DIM / BN, NTOK / BM);   // 32 x 32

    gemm_kernel<0><<<grid_ug, blk>>>(hidden, w_gate, nullptr, H_DIM);
    gemm_kernel<1><<<grid_ug, blk>>>(hidden, w_up,   nullptr, H_DIM);
    gemm_kernel<2><<<grid_dn, blk>>>(nullptr, w_down, out,    I_DIM);
}

// round 3
// speedup vs baseline: 3.3155x; 3.3155x over previous
#include <cuda_runtime.h>
#include <cstdint>
#include <math.h>

// Problem dims (fixed)
#define H_DIM 4096
#define I_DIM 11008
#define NTOK  4096

#define BM 128
#define BN 128
#define BK 32
#define S  4
#define LDSTR 36                       // floats per smem row (128B data + 16B pad)
#define STAGEF (BM * LDSTR)            // floats per matrix per stage
#define NTHREADS 256

// Device scratch
__device__ float g_x[(size_t)NTOK * H_DIM];   // compacted activations (tf32-rounded)
__device__ float g_h[(size_t)NTOK * I_DIM];   // intermediate (silu(gate), then h, tf32-rounded)
__device__ int   g_idx[NTOK];
__device__ int   g_count;

// ---------------------------------------------------------------------------
__device__ __forceinline__ uint32_t cvt_tf32(float x) {
    uint32_t r;
    asm("cvt.rna.tf32.f32 %0, %1;" : "=r"(r) : "f"(x));
    return r;
}
__device__ __forceinline__ void cp16(void* dst_smem, const void* src) {
    uint32_t d = (uint32_t)__cvta_generic_to_shared(dst_smem);
    asm volatile("cp.async.cg.shared.global [%0], [%1], 16;" :: "r"(d), "l"(src) : "memory");
}
#define CP_COMMIT() asm volatile("cp.async.commit_group;" ::: "memory")
#define CP_WAIT(n)  asm volatile("cp.async.wait_group %0;" :: "n"(n) : "memory")

__device__ __forceinline__ void mma8(float* d, const uint32_t* a, const uint32_t* b) {
    asm volatile(
        "mma.sync.aligned.m16n8k8.row.col.f32.tf32.tf32.f32 "
        "{%0,%1,%2,%3}, {%4,%5,%6,%7}, {%8,%9}, {%0,%1,%2,%3};"
        : "+f"(d[0]), "+f"(d[1]), "+f"(d[2]), "+f"(d[3])
        : "r"(a[0]), "r"(a[1]), "r"(a[2]), "r"(a[3]), "r"(b[0]), "r"(b[1]));
}

// ---------------------------------------------------------------------------
// Compaction scan (single block)
// ---------------------------------------------------------------------------
__global__ void compact_kernel(const int* __restrict__ mask) {
    __shared__ int warp_sums[32];
    const int tid = threadIdx.x, lane = tid & 31, warp = tid >> 5;
    int flags[4], cnt = 0;
#pragma unroll
    for (int j = 0; j < 4; ++j) {
        int f = (mask[tid * 4 + j] != 0) ? 1 : 0;
        flags[j] = f; cnt += f;
    }
    int v = cnt;
#pragma unroll
    for (int o = 1; o < 32; o <<= 1) { int n = __shfl_up_sync(~0u, v, o); if (lane >= o) v += n; }
    if (lane == 31) warp_sums[warp] = v;
    __syncthreads();
    if (warp == 0) {
        int s = warp_sums[lane];
#pragma unroll
        for (int o = 1; o < 32; o <<= 1) { int n = __shfl_up_sync(~0u, s, o); if (lane >= o) s += n; }
        warp_sums[lane] = s;
    }
    __syncthreads();
    int base = v - cnt + (warp > 0 ? warp_sums[warp - 1] : 0);
#pragma unroll
    for (int j = 0; j < 4; ++j) if (flags[j]) g_idx[base++] = tid * 4 + j;
    if (tid == 1023) g_count = base;
}

// Gather active rows into g_x with tf32 rounding; zero-pad to 128-row boundary.
__global__ void gather_kernel(const float4* __restrict__ hidden) {
    int row = blockIdx.x;
    int c = g_count;
    int cpad = (c + 127) & ~127;
    if (row >= cpad) return;
    float4* dst = ((float4*)g_x) + (size_t)row * (H_DIM / 4);
    if (row < c) {
        const float4* src = hidden + (size_t)g_idx[row] * (H_DIM / 4);
        for (int i = threadIdx.x; i < H_DIM / 4; i += 256) {
            float4 v = src[i];
            v.x = __uint_as_float(cvt_tf32(v.x));
            v.y = __uint_as_float(cvt_tf32(v.y));
            v.z = __uint_as_float(cvt_tf32(v.z));
            v.w = __uint_as_float(cvt_tf32(v.w));
            dst[i] = v;
        }
    } else {
        float4 z = make_float4(0.f, 0.f, 0.f, 0.f);
        for (int i = threadIdx.x; i < H_DIM / 4; i += 256) dst[i] = z;
    }
}

__global__ void zero_out_kernel(float4* __restrict__ out, int n4) {
    int i = blockIdx.x * blockDim.x + threadIdx.x;
    if (i < n4) out[i] = make_float4(0.f, 0.f, 0.f, 0.f);
}

// ---------------------------------------------------------------------------
// tf32 mma.sync GEMM: C[m,n] = sum_k A[m,k] * B[n,k]
// MODE 0: A=g_x, epilogue g_h = silu(acc)
// MODE 1: A=g_x, epilogue g_h = tf32(g_h * acc)
// MODE 2: A=g_h, epilogue out[g_idx[m]] = acc
// Block 128x128, BK=32, 4-stage cp.async, 8 warps of 64x32.
// ---------------------------------------------------------------------------
template <int MODE>
__global__ __launch_bounds__(NTHREADS, 1)
void mma_gemm(const float* __restrict__ B, float* __restrict__ C, int K)
{
    const int Mc = g_count;
    const int m0 = blockIdx.y * BM;
    if (m0 >= Mc) return;
    const int n0 = blockIdx.x * BN;

    const float* A = (MODE == 2) ? g_h : g_x;

    extern __shared__ float sm[];

    const int tid  = threadIdx.x;
    const int lane = tid & 31;
    const int wid  = tid >> 5;
    const int wm   = wid >> 2;      // 0..1
    const int wn   = wid & 3;       // 0..3
    const int g    = lane >> 2;     // 0..7
    const int c    = lane & 3;      // 0..3

    const int nk = K / BK;

    // loader: 4 A-chunks + 4 B-chunks of 16B per thread per stage
    const float* srcA0 = A + (size_t)m0 * K;
    const float* srcB0 = B + (size_t)n0 * K;

#define ISSUE(t) do {                                                         \
        float* dA = sm + ((t) % S) * 2 * STAGEF;                              \
        float* dB = dA + STAGEF;                                              \
        const size_t kof = (size_t)(t) * BK;                                  \
        _Pragma("unroll")                                                     \
        for (int ii = 0; ii < 4; ++ii) {                                      \
            int id = tid + ii * 256;                                          \
            int row = id >> 3, ch = id & 7;                                   \
            cp16(dA + row * LDSTR + ch * 4, srcA0 + (size_t)row * K + kof + ch * 4); \
            cp16(dB + row * LDSTR + ch * 4, srcB0 + (size_t)row * K + kof + ch * 4); \
        }                                                                     \
    } while (0)

#pragma unroll
    for (int t = 0; t < S - 1; ++t) { ISSUE(t); CP_COMMIT(); }

    float acc[4][4][4];
#pragma unroll
    for (int i = 0; i < 4; ++i)
#pragma unroll
        for (int j = 0; j < 4; ++j)
#pragma unroll
            for (int r = 0; r < 4; ++r) acc[i][j][r] = 0.f;

    for (int t = 0; t < nk; ++t) {
        CP_WAIT(S - 2);
        __syncthreads();
        if (t + S - 1 < nk) ISSUE(t + S - 1);
        CP_COMMIT();

        const float* As = sm + (t % S) * 2 * STAGEF;
        const float* Bs = As + STAGEF;

#pragma unroll
        for (int kk = 0; kk < BK; kk += 8) {
            uint32_t af[4][4];
            uint32_t bf[4][2];
#pragma unroll
            for (int i = 0; i < 4; ++i) {
                int r = wm * 64 + i * 16 + g;
                af[i][0] = __float_as_uint(As[r * LDSTR + kk + c]);
                af[i][1] = __float_as_uint(As[(r + 8) * LDSTR + kk + c]);
                af[i][2] = __float_as_uint(As[r * LDSTR + kk + c + 4]);
                af[i][3] = __float_as_uint(As[(r + 8) * LDSTR + kk + c + 4]);
            }
#pragma unroll
            for (int j = 0; j < 4; ++j) {
                int n = wn * 32 + j * 8 + g;
                bf[j][0] = cvt_tf32(Bs[n * LDSTR + kk + c]);
                bf[j][1] = cvt_tf32(Bs[n * LDSTR + kk + c + 4]);
            }
#pragma unroll
            for (int i = 0; i < 4; ++i)
#pragma unroll
                for (int j = 0; j < 4; ++j)
                    mma8(acc[i][j], af[i], bf[j]);
        }
    }
#undef ISSUE

    // ---- epilogue ----
#pragma unroll
    for (int i = 0; i < 4; ++i) {
#pragma unroll
        for (int h = 0; h < 2; ++h) {
            const int gm = m0 + wm * 64 + i * 16 + g + h * 8;
#pragma unroll
            for (int j = 0; j < 4; ++j) {
                const int gn = n0 + wn * 32 + j * 8 + c * 2;
                float v0 = acc[i][j][h * 2 + 0];
                float v1 = acc[i][j][h * 2 + 1];
                if (MODE == 0) {
                    float* p = g_h + (size_t)gm * I_DIM + gn;
                    float2 o;
                    o.x = v0 / (1.f + __expf(-v0));
                    o.y = v1 / (1.f + __expf(-v1));
                    *(float2*)p = o;
                } else if (MODE == 1) {
                    float* p = g_h + (size_t)gm * I_DIM + gn;
                    float2 s = *(const float2*)p;
                    float2 o;
                    o.x = __uint_as_float(cvt_tf32(s.x * v0));
                    o.y = __uint_as_float(cvt_tf32(s.y * v1));
                    *(float2*)p = o;
                } else {
                    if (gm < Mc) {
                        float* p = C + (size_t)g_idx[gm] * H_DIM + gn;
                        *(float2*)p = make_float2(v0, v1);
                    }
                }
            }
        }
    }
}

// ---------------------------------------------------------------------------
extern "C" void kernel_launch(void* const* d_in, const int* in_sizes, int n_in,
                              void* d_out, int out_size)
{
    const float* hidden = (const float*)d_in[0];
    const float* w_up   = (const float*)d_in[1];
    const float* w_gate = (const float*)d_in[2];
    const float* w_down = (const float*)d_in[3];
    const int*   mask   = (const int*)d_in[4];
    float* out = (float*)d_out;

    const int SMEM = S * 2 * STAGEF * sizeof(float);   // 147456
    cudaFuncSetAttribute(mma_gemm<0>, cudaFuncAttributeMaxDynamicSharedMemorySize, SMEM);
    cudaFuncSetAttribute(mma_gemm<1>, cudaFuncAttributeMaxDynamicSharedMemorySize, SMEM);
    cudaFuncSetAttribute(mma_gemm<2>, cudaFuncAttributeMaxDynamicSharedMemorySize, SMEM);

    compact_kernel<<<1, 1024>>>(mask);
    gather_kernel<<<NTOK, 256>>>((const float4*)hidden);
    const int n4 = (NTOK * H_DIM) / 4;
    zero_out_kernel<<<(n4 + 255) / 256, 256>>>((float4*)out, n4);

    dim3 blk(NTHREADS);
    dim3 grid_ug(I_DIM / BN, NTOK / BM);   // 86 x 32
    dim3 grid_dn(H_DIM / BN, NTOK / BM);   // 32 x 32

    mma_gemm<0><<<grid_ug, blk, SMEM>>>(w_gate, nullptr, H_DIM);
    mma_gemm<1><<<grid_ug, blk, SMEM>>>(w_up,   nullptr, H_DIM);
    mma_gemm<2><<<grid_dn, blk, SMEM>>>(w_down, out,     I_DIM);
}

// round 4
// speedup vs baseline: 3.8028x; 1.1470x over previous
#include <cuda_runtime.h>
#include <cstdint>
#include <math.h>

// Problem dims (fixed)
#define H_DIM 4096
#define I_DIM 11008
#define NTOK  4096

#define BK 32
#define S  3
#define LDSTR 36                        // floats per smem row (128B data + 16B pad)
#define TILE128 (128 * LDSTR)           // floats per 128-row tile
#define TILE256 (256 * LDSTR)
#define NTHREADS 256

// Device scratch
__device__ float g_x[(size_t)NTOK * H_DIM];   // compacted activations (tf32-rounded)
__device__ float g_h[(size_t)NTOK * I_DIM];   // intermediate h (tf32-rounded)
__device__ int   g_idx[NTOK];
__device__ int   g_count;

// ---------------------------------------------------------------------------
__device__ __forceinline__ uint32_t cvt_tf32(float x) {
    uint32_t r;
    asm("cvt.rna.tf32.f32 %0, %1;" : "=r"(r) : "f"(x));
    return r;
}
__device__ __forceinline__ void cp16(void* dst_smem, const void* src) {
    uint32_t d = (uint32_t)__cvta_generic_to_shared(dst_smem);
    asm volatile("cp.async.cg.shared.global [%0], [%1], 16;" :: "r"(d), "l"(src) : "memory");
}
#define CP_COMMIT() asm volatile("cp.async.commit_group;" ::: "memory")
#define CP_WAIT(n)  asm volatile("cp.async.wait_group %0;" :: "n"(n) : "memory")

__device__ __forceinline__ void mma8(float* d, const uint32_t* a, const uint32_t* b) {
    asm volatile(
        "mma.sync.aligned.m16n8k8.row.col.f32.tf32.tf32.f32 "
        "{%0,%1,%2,%3}, {%4,%5,%6,%7}, {%8,%9}, {%0,%1,%2,%3};"
        : "+f"(d[0]), "+f"(d[1]), "+f"(d[2]), "+f"(d[3])
        : "r"(a[0]), "r"(a[1]), "r"(a[2]), "r"(a[3]), "r"(b[0]), "r"(b[1]));
}

// ---------------------------------------------------------------------------
// Compaction scan (single block)
// ---------------------------------------------------------------------------
__global__ void compact_kernel(const int* __restrict__ mask) {
    __shared__ int warp_sums[32];
    const int tid = threadIdx.x, lane = tid & 31, warp = tid >> 5;
    int flags[4], cnt = 0;
#pragma unroll
    for (int j = 0; j < 4; ++j) {
        int f = (mask[tid * 4 + j] != 0) ? 1 : 0;
        flags[j] = f; cnt += f;
    }
    int v = cnt;
#pragma unroll
    for (int o = 1; o < 32; o <<= 1) { int n = __shfl_up_sync(~0u, v, o); if (lane >= o) v += n; }
    if (lane == 31) warp_sums[warp] = v;
    __syncthreads();
    if (warp == 0) {
        int s = warp_sums[lane];
#pragma unroll
        for (int o = 1; o < 32; o <<= 1) { int n = __shfl_up_sync(~0u, s, o); if (lane >= o) s += n; }
        warp_sums[lane] = s;
    }
    __syncthreads();
    int base = v - cnt + (warp > 0 ? warp_sums[warp - 1] : 0);
#pragma unroll
    for (int j = 0; j < 4; ++j) if (flags[j]) g_idx[base++] = tid * 4 + j;
    if (tid == 1023) g_count = base;
}

// Gather active rows into g_x with tf32 rounding; zero-pad to 128-row boundary.
__global__ void gather_kernel(const float4* __restrict__ hidden) {
    int row = blockIdx.x;
    int c = g_count;
    int cpad = (c + 127) & ~127;
    if (row >= cpad) return;
    float4* dst = ((float4*)g_x) + (size_t)row * (H_DIM / 4);
    if (row < c) {
        const float4* src = hidden + (size_t)g_idx[row] * (H_DIM / 4);
        for (int i = threadIdx.x; i < H_DIM / 4; i += 256) {
            float4 v = src[i];
            v.x = __uint_as_float(cvt_tf32(v.x));
            v.y = __uint_as_float(cvt_tf32(v.y));
            v.z = __uint_as_float(cvt_tf32(v.z));
            v.w = __uint_as_float(cvt_tf32(v.w));
            dst[i] = v;
        }
    } else {
        float4 z = make_float4(0.f, 0.f, 0.f, 0.f);
        for (int i = threadIdx.x; i < H_DIM / 4; i += 256) dst[i] = z;
    }
}

__global__ void zero_out_kernel(float4* __restrict__ out, int n4) {
    int i = blockIdx.x * blockDim.x + threadIdx.x;
    if (i < n4) out[i] = make_float4(0.f, 0.f, 0.f, 0.f);
}

// ---------------------------------------------------------------------------
// Fused up+gate GEMM. Block 128x128, 8 warps @ 64x32, two accumulator sets.
// A = g_x [rows,H] (tf32-rounded), Bu = w_up, Bg = w_gate (cvt in-loop).
// Epilogue: g_h = tf32(up * silu(gate)).
// smem/stage: A + Bu + Bg tiles (3 * 18KB), S=3 stages.
// ---------------------------------------------------------------------------
#define STG_F (3 * TILE128)

__global__ __launch_bounds__(NTHREADS, 1)
void fused_upgate_kernel(const float* __restrict__ w_up, const float* __restrict__ w_gate)
{
    const int Mc = g_count;
    const int m0 = blockIdx.y * 128;
    if (m0 >= Mc) return;
    const int n0 = blockIdx.x * 128;

    extern __shared__ float sm[];

    const int tid  = threadIdx.x;
    const int lane = tid & 31;
    const int wid  = tid >> 5;
    const int wm   = wid >> 2;      // 0..1
    const int wn   = wid & 3;       // 0..3
    const int g    = lane >> 2;     // 0..7
    const int c    = lane & 3;      // 0..3

    const int nk = H_DIM / BK;      // 128

    const float* srcA = g_x    + (size_t)m0 * H_DIM;
    const float* srcU = w_up   + (size_t)n0 * H_DIM;
    const float* srcG = w_gate + (size_t)n0 * H_DIM;

#define ISSUE_F(t) do {                                                        \
        float* st = sm + ((t) % S) * STG_F;                                    \
        const size_t kof = (size_t)(t) * BK;                                   \
        _Pragma("unroll")                                                      \
        for (int ii = 0; ii < 4; ++ii) {                                       \
            int id = tid + ii * 256;                                           \
            int row = id >> 3, ch = id & 7;                                    \
            cp16(st + row * LDSTR + ch * 4,                                    \
                 srcA + (size_t)row * H_DIM + kof + ch * 4);                   \
            cp16(st + TILE128 + row * LDSTR + ch * 4,                          \
                 srcU + (size_t)row * H_DIM + kof + ch * 4);                   \
            cp16(st + 2 * TILE128 + row * LDSTR + ch * 4,                      \
                 srcG + (size_t)row * H_DIM + kof + ch * 4);                   \
        }                                                                      \
    } while (0)

#pragma unroll
    for (int t = 0; t < S - 1; ++t) { ISSUE_F(t); CP_COMMIT(); }

    float acc_u[4][4][4], acc_g[4][4][4];
#pragma unroll
    for (int i = 0; i < 4; ++i)
#pragma unroll
        for (int j = 0; j < 4; ++j)
#pragma unroll
            for (int r = 0; r < 4; ++r) { acc_u[i][j][r] = 0.f; acc_g[i][j][r] = 0.f; }

    for (int t = 0; t < nk; ++t) {
        CP_WAIT(S - 2);
        __syncthreads();
        if (t + S - 1 < nk) ISSUE_F(t + S - 1);
        CP_COMMIT();

        const float* As = sm + (t % S) * STG_F;
        const float* Us = As + TILE128;
        const float* Gs = As + 2 * TILE128;

#pragma unroll
        for (int kk = 0; kk < BK; kk += 8) {
            uint32_t af[4][4];
            uint32_t uf[4][2], gf[4][2];
#pragma unroll
            for (int i = 0; i < 4; ++i) {
                int r = wm * 64 + i * 16 + g;
                af[i][0] = __float_as_uint(As[r * LDSTR + kk + c]);
                af[i][1] = __float_as_uint(As[(r + 8) * LDSTR + kk + c]);
                af[i][2] = __float_as_uint(As[r * LDSTR + kk + c + 4]);
                af[i][3] = __float_as_uint(As[(r + 8) * LDSTR + kk + c + 4]);
            }
#pragma unroll
            for (int j = 0; j < 4; ++j) {
                int n = wn * 32 + j * 8 + g;
                uf[j][0] = cvt_tf32(Us[n * LDSTR + kk + c]);
                uf[j][1] = cvt_tf32(Us[n * LDSTR + kk + c + 4]);
                gf[j][0] = cvt_tf32(Gs[n * LDSTR + kk + c]);
                gf[j][1] = cvt_tf32(Gs[n * LDSTR + kk + c + 4]);
            }
#pragma unroll
            for (int i = 0; i < 4; ++i)
#pragma unroll
                for (int j = 0; j < 4; ++j) {
                    mma8(acc_u[i][j], af[i], uf[j]);
                    mma8(acc_g[i][j], af[i], gf[j]);
                }
        }
    }
#undef ISSUE_F

    // epilogue: h = up * silu(gate), round to tf32, store to g_h
#pragma unroll
    for (int i = 0; i < 4; ++i) {
#pragma unroll
        for (int h = 0; h < 2; ++h) {
            const int gm = m0 + wm * 64 + i * 16 + g + h * 8;
            float* rowp = g_h + (size_t)gm * I_DIM;
#pragma unroll
            for (int j = 0; j < 4; ++j) {
                const int gn = n0 + wn * 32 + j * 8 + c * 2;
                float u0 = acc_u[i][j][h * 2 + 0], u1 = acc_u[i][j][h * 2 + 1];
                float gg0 = acc_g[i][j][h * 2 + 0], gg1 = acc_g[i][j][h * 2 + 1];
                float h0 = u0 * (gg0 / (1.f + __expf(-gg0)));
                float h1 = u1 * (gg1 / (1.f + __expf(-gg1)));
                float2 o;
                o.x = __uint_as_float(cvt_tf32(h0));
                o.y = __uint_as_float(cvt_tf32(h1));
                *(float2*)(rowp + gn) = o;
            }
        }
    }
}

// ---------------------------------------------------------------------------
// Down GEMM. Block 256x128, 8 warps @ 64x64 (4m x 2n). A = g_h (tf32-rounded),
// B = w_down (cvt in-loop). Scatter rows to out via g_idx.
// smem/stage: A(256x) + B(128x) tiles, S=3.
// ---------------------------------------------------------------------------
#define STG_D (TILE256 + TILE128)

__global__ __launch_bounds__(NTHREADS, 1)
void down_kernel(const float* __restrict__ w_down, float* __restrict__ out)
{
    const int Mc = g_count;
    const int m0 = blockIdx.y * 256;
    if (m0 >= Mc) return;
    const int n0 = blockIdx.x * 128;

    extern __shared__ float sm[];

    const int tid  = threadIdx.x;
    const int lane = tid & 31;
    const int wid  = tid >> 5;
    const int wm   = wid >> 1;      // 0..3
    const int wn   = wid & 1;       // 0..1
    const int g    = lane >> 2;     // 0..7
    const int c    = lane & 3;      // 0..3

    const int nk = I_DIM / BK;      // 344

    const float* srcA = g_h    + (size_t)m0 * I_DIM;
    const float* srcB = w_down + (size_t)n0 * I_DIM;

#define ISSUE_D(t) do {                                                        \
        float* st = sm + ((t) % S) * STG_D;                                    \
        const size_t kof = (size_t)(t) * BK;                                   \
        _Pragma("unroll")                                                      \
        for (int ii = 0; ii < 8; ++ii) {                                       \
            int id = tid + ii * 256;                                           \
            int row = id >> 3, ch = id & 7;                                    \
            cp16(st + row * LDSTR + ch * 4,                                    \
                 srcA + (size_t)row * I_DIM + kof + ch * 4);                   \
        }                                                                      \
        _Pragma("unroll")                                                      \
        for (int ii = 0; ii < 4; ++ii) {                                       \
            int id = tid + ii * 256;                                           \
            int row = id >> 3, ch = id & 7;                                    \
            cp16(st + TILE256 + row * LDSTR + ch * 4,                          \
                 srcB + (size_t)row * I_DIM + kof + ch * 4);                   \
        }                                                                      \
    } while (0)

#pragma unroll
    for (int t = 0; t < S - 1; ++t) { ISSUE_D(t); CP_COMMIT(); }

    float acc[4][8][4];
#pragma unroll
    for (int i = 0; i < 4; ++i)
#pragma unroll
        for (int j = 0; j < 8; ++j)
#pragma unroll
            for (int r = 0; r < 4; ++r) acc[i][j][r] = 0.f;

    for (int t = 0; t < nk; ++t) {
        CP_WAIT(S - 2);
        __syncthreads();
        if (t + S - 1 < nk) ISSUE_D(t + S - 1);
        CP_COMMIT();

        const float* As = sm + (t % S) * STG_D;
        const float* Bs = As + TILE256;

#pragma unroll
        for (int kk = 0; kk < BK; kk += 8) {
            uint32_t af[4][4];
            uint32_t bf[8][2];
#pragma unroll
            for (int i = 0; i < 4; ++i) {
                int r = wm * 64 + i * 16 + g;
                af[i][0] = __float_as_uint(As[r * LDSTR + kk + c]);
                af[i][1] = __float_as_uint(As[(r + 8) * LDSTR + kk + c]);
                af[i][2] = __float_as_uint(As[r * LDSTR + kk + c + 4]);
                af[i][3] = __float_as_uint(As[(r + 8) * LDSTR + kk + c + 4]);
            }
#pragma unroll
            for (int j = 0; j < 8; ++j) {
                int n = wn * 64 + j * 8 + g;
                bf[j][0] = cvt_tf32(Bs[n * LDSTR + kk + c]);
                bf[j][1] = cvt_tf32(Bs[n * LDSTR + kk + c + 4]);
            }
#pragma unroll
            for (int i = 0; i < 4; ++i)
#pragma unroll
                for (int j = 0; j < 8; ++j)
                    mma8(acc[i][j], af[i], bf[j]);
        }
    }
#undef ISSUE_D

    // epilogue: scatter
#pragma unroll
    for (int i = 0; i < 4; ++i) {
#pragma unroll
        for (int h = 0; h < 2; ++h) {
            const int gm = m0 + wm * 64 + i * 16 + g + h * 8;
            if (gm < Mc) {
                float* rowp = out + (size_t)g_idx[gm] * H_DIM;
#pragma unroll
                for (int j = 0; j < 8; ++j) {
                    const int gn = n0 + wn * 64 + j * 8 + c * 2;
                    *(float2*)(rowp + gn) =
                        make_float2(acc[i][j][h * 2 + 0], acc[i][j][h * 2 + 1]);
                }
            }
        }
    }
}

// ---------------------------------------------------------------------------
extern "C" void kernel_launch(void* const* d_in, const int* in_sizes, int n_in,
                              void* d_out, int out_size)
{
    const float* hidden = (const float*)d_in[0];
    const float* w_up   = (const float*)d_in[1];
    const float* w_gate = (const float*)d_in[2];
    const float* w_down = (const float*)d_in[3];
    const int*   mask   = (const int*)d_in[4];
    float* out = (float*)d_out;

    const int SMEM_F = S * STG_F * sizeof(float);   // 165888
    const int SMEM_D = S * STG_D * sizeof(float);   // 165888
    cudaFuncSetAttribute(fused_upgate_kernel, cudaFuncAttributeMaxDynamicSharedMemorySize, SMEM_F);
    cudaFuncSetAttribute(down_kernel,         cudaFuncAttributeMaxDynamicSharedMemorySize, SMEM_D);

    compact_kernel<<<1, 1024>>>(mask);
    gather_kernel<<<NTOK, 256>>>((const float4*)hidden);
    const int n4 = (NTOK * H_DIM) / 4;
    zero_out_kernel<<<(n4 + 255) / 256, 256>>>((float4*)out, n4);

    dim3 blk(NTHREADS);
    fused_upgate_kernel<<<dim3(I_DIM / 128, NTOK / 128), blk, SMEM_F>>>(w_up, w_gate);
    down_kernel<<<dim3(H_DIM / 128, NTOK / 256), blk, SMEM_D>>>(w_down, out);
}

// round 5
// speedup vs baseline: 3.9372x; 1.0354x over previous
#include <cuda_runtime.h>
#include <cstdint>
#include <math.h>

// Problem dims (fixed)
#define H_DIM 4096
#define I_DIM 11008
#define NTOK  4096

#define BK 32
#define S  3
#define LDSTR 40                        // floats per smem row (128B data + 32B pad)
#define TILE128 (128 * LDSTR)
#define TILE256 (256 * LDSTR)
#define NTHREADS 256

// Device scratch (k-interleaved tf32 layouts; interleave within each 8-float
// group: natural k stored at position 2*(k&3) + (k>>2), i.e. [0,4,1,5,2,6,3,7])
__device__ float g_x[(size_t)NTOK * H_DIM];
__device__ float g_h[(size_t)NTOK * I_DIM];
__device__ float g_wu[(size_t)I_DIM * H_DIM];
__device__ float g_wg[(size_t)I_DIM * H_DIM];
__device__ float g_wd[(size_t)H_DIM * I_DIM];
__device__ int   g_idx[NTOK];
__device__ int   g_count;

// ---------------------------------------------------------------------------
__device__ __forceinline__ float cvt_tf32f(float x) {
    uint32_t r;
    asm("cvt.rna.tf32.f32 %0, %1;" : "=r"(r) : "f"(x));
    return __uint_as_float(r);
}
__device__ __forceinline__ void cp16(void* dst_smem, const void* src) {
    uint32_t d = (uint32_t)__cvta_generic_to_shared(dst_smem);
    asm volatile("cp.async.cg.shared.global [%0], [%1], 16;" :: "r"(d), "l"(src) : "memory");
}
#define CP_COMMIT() asm volatile("cp.async.commit_group;" ::: "memory")
#define CP_WAIT(n)  asm volatile("cp.async.wait_group %0;" :: "n"(n) : "memory")

__device__ __forceinline__ void mma8(float* d, const uint32_t* a, const uint32_t* b) {
    asm volatile(
        "mma.sync.aligned.m16n8k8.row.col.f32.tf32.tf32.f32 "
        "{%0,%1,%2,%3}, {%4,%5,%6,%7}, {%8,%9}, {%0,%1,%2,%3};"
        : "+f"(d[0]), "+f"(d[1]), "+f"(d[2]), "+f"(d[3])
        : "r"(a[0]), "r"(a[1]), "r"(a[2]), "r"(a[3]), "r"(b[0]), "r"(b[1]));
}

// interleaved position of natural k within its 8-group
__device__ __forceinline__ int perm8(int k) { return ((k & 3) << 1) | ((k >> 2) & 1); }

// A-fragment: 4 m16 tiles, rows rbase+i*16+g / +8, k = kk+c, kk+c+4 (interleaved LDS.64)
__device__ __forceinline__ void load_afrag(const float* As, int rbase, int kk, int c,
                                           uint32_t af[4][4]) {
#pragma unroll
    for (int i = 0; i < 4; ++i) {
        const int r = rbase + i * 16;
        float2 lo = *(const float2*)(As + r * LDSTR + kk + 2 * c);
        float2 hi = *(const float2*)(As + (r + 8) * LDSTR + kk + 2 * c);
        af[i][0] = __float_as_uint(lo.x);
        af[i][1] = __float_as_uint(hi.x);
        af[i][2] = __float_as_uint(lo.y);
        af[i][3] = __float_as_uint(hi.y);
    }
}
// B-fragment: NJ n8 tiles, row nbase+j*8+g
template <int NJ>
__device__ __forceinline__ void load_bfrag(const float* Bs, int nbase, int kk, int c,
                                           uint32_t bf[NJ][2]) {
#pragma unroll
    for (int j = 0; j < NJ; ++j) {
        float2 b = *(const float2*)(Bs + (nbase + j * 8) * LDSTR + kk + 2 * c);
        bf[j][0] = __float_as_uint(b.x);
        bf[j][1] = __float_as_uint(b.y);
    }
}

// ---------------------------------------------------------------------------
// Compaction scan (single block)
// ---------------------------------------------------------------------------
__global__ void compact_kernel(const int* __restrict__ mask) {
    __shared__ int warp_sums[32];
    const int tid = threadIdx.x, lane = tid & 31, warp = tid >> 5;
    int flags[4], cnt = 0;
#pragma unroll
    for (int j = 0; j < 4; ++j) {
        int f = (mask[tid * 4 + j] != 0) ? 1 : 0;
        flags[j] = f; cnt += f;
    }
    int v = cnt;
#pragma unroll
    for (int o = 1; o < 32; o <<= 1) { int n = __shfl_up_sync(~0u, v, o); if (lane >= o) v += n; }
    if (lane == 31) warp_sums[warp] = v;
    __syncthreads();
    if (warp == 0) {
        int s = warp_sums[lane];
#pragma unroll
        for (int o = 1; o < 32; o <<= 1) { int n = __shfl_up_sync(~0u, s, o); if (lane >= o) s += n; }
        warp_sums[lane] = s;
    }
    __syncthreads();
    int base = v - cnt + (warp > 0 ? warp_sums[warp - 1] : 0);
#pragma unroll
    for (int j = 0; j < 4; ++j) if (flags[j]) g_idx[base++] = tid * 4 + j;
    if (tid == 1023) g_count = base;
}

// ---------------------------------------------------------------------------
// cvt.rna + 8-group interleave:  out = perm(tf32(in))
// ---------------------------------------------------------------------------
__device__ __forceinline__ void perm_pair(float4 i0, float4 i1, float4& o0, float4& o1) {
    o0.x = cvt_tf32f(i0.x); o0.y = cvt_tf32f(i1.x);
    o0.z = cvt_tf32f(i0.y); o0.w = cvt_tf32f(i1.y);
    o1.x = cvt_tf32f(i0.z); o1.y = cvt_tf32f(i1.z);
    o1.z = cvt_tf32f(i0.w); o1.w = cvt_tf32f(i1.w);
}

__global__ void cvt_permute_kernel(const float4* __restrict__ src, float4* __restrict__ dst,
                                   int ngroups) {
    int i = blockIdx.x * blockDim.x + threadIdx.x;
    int stride = gridDim.x * blockDim.x;
    for (; i < ngroups; i += stride) {
        float4 i0 = src[2 * i], i1 = src[2 * i + 1];
        float4 o0, o1;
        perm_pair(i0, i1, o0, o1);
        dst[2 * i] = o0; dst[2 * i + 1] = o1;
    }
}

// Gather active rows into g_x (tf32 + interleave); zero-pad to 128-row boundary.
__global__ void gather_kernel(const float4* __restrict__ hidden) {
    int row = blockIdx.x;
    int c = g_count;
    int cpad = (c + 127) & ~127;
    if (row >= cpad) return;
    float4* dst = ((float4*)g_x) + (size_t)row * (H_DIM / 4);
    if (row < c) {
        const float4* src = hidden + (size_t)g_idx[row] * (H_DIM / 4);
        for (int i = threadIdx.x; i < H_DIM / 8; i += 256) {
            float4 i0 = src[2 * i], i1 = src[2 * i + 1];
            float4 o0, o1;
            perm_pair(i0, i1, o0, o1);
            dst[2 * i] = o0; dst[2 * i + 1] = o1;
        }
    } else {
        float4 z = make_float4(0.f, 0.f, 0.f, 0.f);
        for (int i = threadIdx.x; i < H_DIM / 4; i += 256) dst[i] = z;
    }
}

__global__ void zero_out_kernel(float4* __restrict__ out, int n4) {
    int i = blockIdx.x * blockDim.x + threadIdx.x;
    if (i < n4) out[i] = make_float4(0.f, 0.f, 0.f, 0.f);
}

// ---------------------------------------------------------------------------
// Fused up+gate GEMM. Block 128x128, 8 warps @ 64x32, dual accumulators.
// All operands pre-tf32 + k-interleaved. Epilogue: g_h = tf32(up*silu(gate)),
// written in interleaved layout for the down GEMM.
// ---------------------------------------------------------------------------
#define STG_F (3 * TILE128)

__global__ __launch_bounds__(NTHREADS, 1)
void fused_upgate_kernel()
{
    const int Mc = g_count;
    const int m0 = blockIdx.y * 128;
    if (m0 >= Mc) return;
    const int n0 = blockIdx.x * 128;

    extern __shared__ float sm[];

    const int tid  = threadIdx.x;
    const int lane = tid & 31;
    const int wid  = tid >> 5;
    const int wm   = wid >> 2;
    const int wn   = wid & 3;
    const int g    = lane >> 2;
    const int c    = lane & 3;

    const int nk = H_DIM / BK;      // 128

    const float* srcA = g_x  + (size_t)m0 * H_DIM;
    const float* srcU = g_wu + (size_t)n0 * H_DIM;
    const float* srcG = g_wg + (size_t)n0 * H_DIM;

#define ISSUE_F(t) do {                                                        \
        float* st = sm + ((t) % S) * STG_F;                                    \
        const size_t kof = (size_t)(t) * BK;                                   \
        _Pragma("unroll")                                                      \
        for (int ii = 0; ii < 4; ++ii) {                                       \
            int id = tid + ii * 256;                                           \
            int row = id >> 3, ch = id & 7;                                    \
            cp16(st + row * LDSTR + ch * 4,                                    \
                 srcA + (size_t)row * H_DIM + kof + ch * 4);                   \
            cp16(st + TILE128 + row * LDSTR + ch * 4,                          \
                 srcU + (size_t)row * H_DIM + kof + ch * 4);                   \
            cp16(st + 2 * TILE128 + row * LDSTR + ch * 4,                      \
                 srcG + (size_t)row * H_DIM + kof + ch * 4);                   \
        }                                                                      \
    } while (0)

#pragma unroll
    for (int t = 0; t < S - 1; ++t) { ISSUE_F(t); CP_COMMIT(); }

    float acc_u[4][4][4], acc_g[4][4][4];
#pragma unroll
    for (int i = 0; i < 4; ++i)
#pragma unroll
        for (int j = 0; j < 4; ++j)
#pragma unroll
            for (int r = 0; r < 4; ++r) { acc_u[i][j][r] = 0.f; acc_g[i][j][r] = 0.f; }

    uint32_t af[2][4][4], uf[2][4][2], gf[2][4][2];
    const int rbase = wm * 64 + g;
    const int nbase = wn * 32 + g;

    for (int t = 0; t < nk; ++t) {
        CP_WAIT(S - 2);
        __syncthreads();
        if (t + S - 1 < nk) ISSUE_F(t + S - 1);
        CP_COMMIT();

        const float* As = sm + (t % S) * STG_F;
        const float* Us = As + TILE128;
        const float* Gs = As + 2 * TILE128;

        load_afrag(As, rbase, 0, c, af[0]);
        load_bfrag<4>(Us, nbase, 0, c, uf[0]);
        load_bfrag<4>(Gs, nbase, 0, c, gf[0]);

#pragma unroll
        for (int kk4 = 0; kk4 < 4; ++kk4) {
            const int cur = kk4 & 1;
            if (kk4 < 3) {
                load_afrag(As, rbase, (kk4 + 1) * 8, c, af[cur ^ 1]);
                load_bfrag<4>(Us, nbase, (kk4 + 1) * 8, c, uf[cur ^ 1]);
                load_bfrag<4>(Gs, nbase, (kk4 + 1) * 8, c, gf[cur ^ 1]);
            }
#pragma unroll
            for (int i = 0; i < 4; ++i)
#pragma unroll
                for (int j = 0; j < 4; ++j) {
                    mma8(acc_u[i][j], af[cur][i], uf[cur][j]);
                    mma8(acc_g[i][j], af[cur][i], gf[cur][j]);
                }
        }
    }
#undef ISSUE_F

    // epilogue: h = up*silu(gate), tf32-round, store interleaved
#pragma unroll
    for (int i = 0; i < 4; ++i) {
#pragma unroll
        for (int h = 0; h < 2; ++h) {
            const int gm = m0 + wm * 64 + i * 16 + g + h * 8;
            float* rowp = g_h + (size_t)gm * I_DIM;
#pragma unroll
            for (int j = 0; j < 4; ++j) {
                const int grp = n0 + wn * 32 + j * 8;   // 8-group base
                const int k0 = c * 2, k1 = c * 2 + 1;
                float u0 = acc_u[i][j][h * 2 + 0], u1 = acc_u[i][j][h * 2 + 1];
                float gg0 = acc_g[i][j][h * 2 + 0], gg1 = acc_g[i][j][h * 2 + 1];
                float h0 = u0 * (gg0 / (1.f + __expf(-gg0)));
                float h1 = u1 * (gg1 / (1.f + __expf(-gg1)));
                rowp[grp + perm8(k0)] = cvt_tf32f(h0);
                rowp[grp + perm8(k1)] = cvt_tf32f(h1);
            }
        }
    }
}

// ---------------------------------------------------------------------------
// Down GEMM. Block 256x128, 8 warps @ 64x64 (4m x 2n). A = g_h, B = g_wd
// (both pre-tf32 + interleaved). Scatter rows to out via g_idx.
// ---------------------------------------------------------------------------
#define STG_D (TILE256 + TILE128)

__global__ __launch_bounds__(NTHREADS, 1)
void down_kernel(float* __restrict__ out)
{
    const int Mc = g_count;
    const int m0 = blockIdx.y * 256;
    if (m0 >= Mc) return;
    const int n0 = blockIdx.x * 128;

    extern __shared__ float sm[];

    const int tid  = threadIdx.x;
    const int lane = tid & 31;
    const int wid  = tid >> 5;
    const int wm   = wid >> 1;      // 0..3
    const int wn   = wid & 1;       // 0..1
    const int g    = lane >> 2;
    const int c    = lane & 3;

    const int nk = I_DIM / BK;      // 344

    const float* srcA = g_h  + (size_t)m0 * I_DIM;
    const float* srcB = g_wd + (size_t)n0 * I_DIM;

#define ISSUE_D(t) do {                                                        \
        float* st = sm + ((t) % S) * STG_D;                                    \
        const size_t kof = (size_t)(t) * BK;                                   \
        _Pragma("unroll")                                                      \
        for (int ii = 0; ii < 8; ++ii) {                                       \
            int id = tid + ii * 256;                                           \
            int row = id >> 3, ch = id & 7;                                    \
            cp16(st + row * LDSTR + ch * 4,                                    \
                 srcA + (size_t)row * I_DIM + kof + ch * 4);                   \
        }                                                                      \
        _Pragma("unroll")                                                      \
        for (int ii = 0; ii < 4; ++ii) {                                       \
            int id = tid + ii * 256;                                           \
            int row = id >> 3, ch = id & 7;                                    \
            cp16(st + TILE256 + row * LDSTR + ch * 4,                          \
                 srcB + (size_t)row * I_DIM + kof + ch * 4);                   \
        }                                                                      \
    } while (0)

#pragma unroll
    for (int t = 0; t < S - 1; ++t) { ISSUE_D(t); CP_COMMIT(); }

    float acc[4][8][4];
#pragma unroll
    for (int i = 0; i < 4; ++i)
#pragma unroll
        for (int j = 0; j < 8; ++j)
#pragma unroll
            for (int r = 0; r < 4; ++r) acc[i][j][r] = 0.f;

    uint32_t af[2][4][4], bf[2][8][2];
    const int rbase = wm * 64 + g;
    const int nbase = wn * 64 + g;

    for (int t = 0; t < nk; ++t) {
        CP_WAIT(S - 2);
        __syncthreads();
        if (t + S - 1 < nk) ISSUE_D(t + S - 1);
        CP_COMMIT();

        const float* As = sm + (t % S) * STG_D;
        const float* Bs = As + TILE256;

        load_afrag(As, rbase, 0, c, af[0]);
        load_bfrag<8>(Bs, nbase, 0, c, bf[0]);

#pragma unroll
        for (int kk4 = 0; kk4 < 4; ++kk4) {
            const int cur = kk4 & 1;
            if (kk4 < 3) {
                load_afrag(As, rbase, (kk4 + 1) * 8, c, af[cur ^ 1]);
                load_bfrag<8>(Bs, nbase, (kk4 + 1) * 8, c, bf[cur ^ 1]);
            }
#pragma unroll
            for (int i = 0; i < 4; ++i)
#pragma unroll
                for (int j = 0; j < 8; ++j)
                    mma8(acc[i][j], af[cur][i], bf[cur][j]);
        }
    }
#undef ISSUE_D

    // epilogue: scatter (natural layout)
#pragma unroll
    for (int i = 0; i < 4; ++i) {
#pragma unroll
        for (int h = 0; h < 2; ++h) {
            const int gm = m0 + wm * 64 + i * 16 + g + h * 8;
            if (gm < Mc) {
                float* rowp = out + (size_t)g_idx[gm] * H_DIM;
#pragma unroll
                for (int j = 0; j < 8; ++j) {
                    const int gn = n0 + wn * 64 + j * 8 + c * 2;
                    *(float2*)(rowp + gn) =
                        make_float2(acc[i][j][h * 2 + 0], acc[i][j][h * 2 + 1]);
                }
            }
        }
    }
}

// ---------------------------------------------------------------------------
extern "C" void kernel_launch(void* const* d_in, const int* in_sizes, int n_in,
                              void* d_out, int out_size)
{
    const float* hidden = (const float*)d_in[0];
    const float* w_up   = (const float*)d_in[1];
    const float* w_gate = (const float*)d_in[2];
    const float* w_down = (const float*)d_in[3];
    const int*   mask   = (const int*)d_in[4];
    float* out = (float*)d_out;

    const int SMEM_F = S * STG_F * sizeof(float);   // 184320
    const int SMEM_D = S * STG_D * sizeof(float);   // 184320
    cudaFuncSetAttribute(fused_upgate_kernel, cudaFuncAttributeMaxDynamicSharedMemorySize, SMEM_F);
    cudaFuncSetAttribute(down_kernel,         cudaFuncAttributeMaxDynamicSharedMemorySize, SMEM_D);

    float *d_wu, *d_wg, *d_wd;
    cudaGetSymbolAddress((void**)&d_wu, g_wu);
    cudaGetSymbolAddress((void**)&d_wg, g_wg);
    cudaGetSymbolAddress((void**)&d_wd, g_wd);

    compact_kernel<<<1, 1024>>>(mask);
    gather_kernel<<<NTOK, 256>>>((const float4*)hidden);

    const int wg_groups = (I_DIM * H_DIM) / 8;   // 5,636,096
    cvt_permute_kernel<<<4096, 256>>>((const float4*)w_up,   (float4*)d_wu, wg_groups);
    cvt_permute_kernel<<<4096, 256>>>((const float4*)w_gate, (float4*)d_wg, wg_groups);
    cvt_permute_kernel<<<4096, 256>>>((const float4*)w_down, (float4*)d_wd, wg_groups);

    const int n4 = (NTOK * H_DIM) / 4;
    zero_out_kernel<<<(n4 + 255) / 256, 256>>>((float4*)out, n4);

    dim3 blk(NTHREADS);
    fused_upgate_kernel<<<dim3(I_DIM / 128, NTOK / 128), blk, SMEM_F>>>();
    down_kernel<<<dim3(H_DIM / 128, NTOK / 256), blk, SMEM_D>>>(out);
}

// round 7
// speedup vs baseline: 7.5949x; 1.9290x over previous
#include <cuda_runtime.h>
#include <cuda_fp16.h>
#include <cstdint>
#include <math.h>

// Problem dims (fixed)
#define H_DIM 4096
#define I_DIM 11008
#define NTOK  4096

#define BKH 64                          // halves per pipeline stage (128B rows)
#define S  3
#define LDSTR 80                        // halves per smem row (128B data + 32B pad)
#define TILE128 (128 * LDSTR)           // halves
#define TILE256 (256 * LDSTR)
#define NTHREADS 256

// Device scratch. All fp16 operands use 16-group k-interleave:
// natural k (0..15) stored at pos 4*((k>>1)&3) + 2*(k>>3) + (k&1),
// i.e. layout [0,1,8,9,2,3,10,11,4,5,12,13,6,7,14,15].
__device__ __half g_x[(size_t)NTOK * H_DIM];
__device__ __half g_h[(size_t)NTOK * I_DIM];
__device__ __half g_wu[(size_t)I_DIM * H_DIM];
__device__ __half g_wg[(size_t)I_DIM * H_DIM];
__device__ __half g_wd[(size_t)H_DIM * I_DIM];
__device__ int    g_idx[NTOK];
__device__ int    g_count;

// ---------------------------------------------------------------------------
__device__ __forceinline__ uint32_t h2_as_u32(__half2 h) {
    return *reinterpret_cast<uint32_t*>(&h);
}
__device__ __forceinline__ void cp16(void* dst_smem, const void* src) {
    uint32_t d = (uint32_t)__cvta_generic_to_shared(dst_smem);
    asm volatile("cp.async.cg.shared.global [%0], [%1], 16;" :: "r"(d), "l"(src) : "memory");
}
#define CP_COMMIT() asm volatile("cp.async.commit_group;" ::: "memory")
#define CP_WAIT(n)  asm volatile("cp.async.wait_group %0;" :: "n"(n) : "memory")

__device__ __forceinline__ void mma16(float* d, const uint32_t* a, const uint32_t* b) {
    asm volatile(
        "mma.sync.aligned.m16n8k16.row.col.f32.f16.f16.f32 "
        "{%0,%1,%2,%3}, {%4,%5,%6,%7}, {%8,%9}, {%0,%1,%2,%3};"
        : "+f"(d[0]), "+f"(d[1]), "+f"(d[2]), "+f"(d[3])
        : "r"(a[0]), "r"(a[1]), "r"(a[2]), "r"(a[3]), "r"(b[0]), "r"(b[1]));
}

// A-fragment: 4 m16 tiles; one LDS.64 per (row, kgroup) yields a0+a2 / a1+a3.
__device__ __forceinline__ void load_afrag(const __half* As, int rbase, int kg, int c,
                                           uint32_t af[4][4]) {
#pragma unroll
    for (int i = 0; i < 4; ++i) {
        const int r = rbase + i * 16;
        uint2 lo = *(const uint2*)(As + r * LDSTR + kg * 16 + 4 * c);
        uint2 hi = *(const uint2*)(As + (r + 8) * LDSTR + kg * 16 + 4 * c);
        af[i][0] = lo.x; af[i][1] = hi.x; af[i][2] = lo.y; af[i][3] = hi.y;
    }
}
template <int NJ>
__device__ __forceinline__ void load_bfrag(const __half* Bs, int nbase, int kg, int c,
                                           uint32_t bf[NJ][2]) {
#pragma unroll
    for (int j = 0; j < NJ; ++j) {
        uint2 v = *(const uint2*)(Bs + (nbase + j * 8) * LDSTR + kg * 16 + 4 * c);
        bf[j][0] = v.x; bf[j][1] = v.y;
    }
}

// ---------------------------------------------------------------------------
// Compaction scan (single block)
// ---------------------------------------------------------------------------
__global__ void compact_kernel(const int* __restrict__ mask) {
    __shared__ int warp_sums[32];
    const int tid = threadIdx.x, lane = tid & 31, warp = tid >> 5;
    int flags[4], cnt = 0;
#pragma unroll
    for (int j = 0; j < 4; ++j) {
        int f = (mask[tid * 4 + j] != 0) ? 1 : 0;
        flags[j] = f; cnt += f;
    }
    int v = cnt;
#pragma unroll
    for (int o = 1; o < 32; o <<= 1) { int n = __shfl_up_sync(~0u, v, o); if (lane >= o) v += n; }
    if (lane == 31) warp_sums[warp] = v;
    __syncthreads();
    if (warp == 0) {
        int s = warp_sums[lane];
#pragma unroll
        for (int o = 1; o < 32; o <<= 1) { int n = __shfl_up_sync(~0u, s, o); if (lane >= o) s += n; }
        warp_sums[lane] = s;
    }
    __syncthreads();
    int base = v - cnt + (warp > 0 ? warp_sums[warp - 1] : 0);
#pragma unroll
    for (int j = 0; j < 4; ++j) if (flags[j]) g_idx[base++] = tid * 4 + j;
    if (tid == 1023) g_count = base;
}

// ---------------------------------------------------------------------------
// fp32 -> fp16 with 16-group interleave. One 16-group per thread-iteration.
// output halves: [f0.xy, f2.xy, f0.zw, f2.zw, f1.xy, f3.xy, f1.zw, f3.zw]
// ---------------------------------------------------------------------------
__device__ __forceinline__ void cvt_group(const float4* s, uint4* d) {
    float4 f0 = s[0], f1 = s[1], f2 = s[2], f3 = s[3];
    uint4 o0, o1;
    o0.x = h2_as_u32(__floats2half2_rn(f0.x, f0.y));
    o0.y = h2_as_u32(__floats2half2_rn(f2.x, f2.y));
    o0.z = h2_as_u32(__floats2half2_rn(f0.z, f0.w));
    o0.w = h2_as_u32(__floats2half2_rn(f2.z, f2.w));
    o1.x = h2_as_u32(__floats2half2_rn(f1.x, f1.y));
    o1.y = h2_as_u32(__floats2half2_rn(f3.x, f3.y));
    o1.z = h2_as_u32(__floats2half2_rn(f1.z, f1.w));
    o1.w = h2_as_u32(__floats2half2_rn(f3.z, f3.w));
    d[0] = o0; d[1] = o1;
}

__global__ void cvt_permute_kernel(const float4* __restrict__ src, uint4* __restrict__ dst,
                                   int ngroups) {
    int i = blockIdx.x * blockDim.x + threadIdx.x;
    int stride = gridDim.x * blockDim.x;
    for (; i < ngroups; i += stride) cvt_group(src + 4 * i, dst + 2 * i);
}

// Gather active rows into g_x (fp16 + interleave); zero-pad to 128-row boundary.
__global__ void gather_kernel(const float4* __restrict__ hidden) {
    int row = blockIdx.x;
    int c = g_count;
    int cpad = (c + 127) & ~127;
    if (row >= cpad) return;
    uint4* dst = (uint4*)(g_x + (size_t)row * H_DIM);
    if (row < c) {
        const float4* src = hidden + (size_t)g_idx[row] * (H_DIM / 4);
        for (int i = threadIdx.x; i < H_DIM / 16; i += 256)
            cvt_group(src + 4 * i, dst + 2 * i);
    } else {
        uint4 z = make_uint4(0, 0, 0, 0);
        for (int i = threadIdx.x; i < H_DIM / 8; i += 256) dst[i] = z;
    }
}

__global__ void zero_out_kernel(float4* __restrict__ out, int n4) {
    int i = blockIdx.x * blockDim.x + threadIdx.x;
    if (i < n4) out[i] = make_float4(0.f, 0.f, 0.f, 0.f);
}

// ---------------------------------------------------------------------------
// Fused up+gate GEMM. Block 128x128, 8 warps @ 64x32, dual accumulators.
// fp16 operands, fp32 accum. Epilogue: g_h = fp16(up*silu(gate)) interleaved.
// ---------------------------------------------------------------------------
#define STG_F (3 * TILE128)   // halves per stage

__global__ __launch_bounds__(NTHREADS, 1)
void fused_upgate_kernel()
{
    const int Mc = g_count;
    const int m0 = blockIdx.y * 128;
    if (m0 >= Mc) return;
    const int n0 = blockIdx.x * 128;

    extern __shared__ __half smh[];

    const int tid  = threadIdx.x;
    const int lane = tid & 31;
    const int wid  = tid >> 5;
    const int wm   = wid >> 2;
    const int wn   = wid & 3;
    const int g    = lane >> 2;
    const int c    = lane & 3;

    const int nk = H_DIM / BKH;      // 64

    const __half* srcA = g_x  + (size_t)m0 * H_DIM;
    const __half* srcU = g_wu + (size_t)n0 * H_DIM;
    const __half* srcG = g_wg + (size_t)n0 * H_DIM;

#define ISSUE_F(t) do {                                                        \
        __half* st = smh + ((t) % S) * STG_F;                                   \
        const size_t kof = (size_t)(t) * BKH;                                  \
        _Pragma("unroll")                                                      \
        for (int ii = 0; ii < 4; ++ii) {                                       \
            int id = tid + ii * 256;                                           \
            int row = id >> 3, ch = id & 7;                                    \
            cp16(st + row * LDSTR + ch * 8,                                    \
                 srcA + (size_t)row * H_DIM + kof + ch * 8);                   \
            cp16(st + TILE128 + row * LDSTR + ch * 8,                          \
                 srcU + (size_t)row * H_DIM + kof + ch * 8);                   \
            cp16(st + 2 * TILE128 + row * LDSTR + ch * 8,                      \
                 srcG + (size_t)row * H_DIM + kof + ch * 8);                   \
        }                                                                      \
    } while (0)

#pragma unroll
    for (int t = 0; t < S - 1; ++t) { ISSUE_F(t); CP_COMMIT(); }

    float acc_u[4][4][4], acc_g[4][4][4];
#pragma unroll
    for (int i = 0; i < 4; ++i)
#pragma unroll
        for (int j = 0; j < 4; ++j)
#pragma unroll
            for (int r = 0; r < 4; ++r) { acc_u[i][j][r] = 0.f; acc_g[i][j][r] = 0.f; }

    uint32_t af[2][4][4], uf[2][4][2], gf[2][4][2];
    const int rbase = wm * 64 + g;
    const int nbase = wn * 32 + g;

    for (int t = 0; t < nk; ++t) {
        CP_WAIT(S - 2);
        __syncthreads();
        if (t + S - 1 < nk) ISSUE_F(t + S - 1);
        CP_COMMIT();

        const __half* As = smh + (t % S) * STG_F;
        const __half* Us = As + TILE128;
        const __half* Gs = As + 2 * TILE128;

        load_afrag(As, rbase, 0, c, af[0]);
        load_bfrag<4>(Us, nbase, 0, c, uf[0]);
        load_bfrag<4>(Gs, nbase, 0, c, gf[0]);

#pragma unroll
        for (int kg = 0; kg < 4; ++kg) {
            const int cur = kg & 1;
            if (kg < 3) {
                load_afrag(As, rbase, kg + 1, c, af[cur ^ 1]);
                load_bfrag<4>(Us, nbase, kg + 1, c, uf[cur ^ 1]);
                load_bfrag<4>(Gs, nbase, kg + 1, c, gf[cur ^ 1]);
            }
#pragma unroll
            for (int i = 0; i < 4; ++i)
#pragma unroll
                for (int j = 0; j < 4; ++j) {
                    mma16(acc_u[i][j], af[cur][i], uf[cur][j]);
                    mma16(acc_g[i][j], af[cur][i], gf[cur][j]);
                }
        }
    }
#undef ISSUE_F

    // epilogue: h = up*silu(gate) -> fp16, interleaved store into g_h.
    // cols 2c,2c+1 of j-tile land at interleaved offset 4c + 2*(j&1) within
    // the 16-group based at (j>>1)*16.
#pragma unroll
    for (int i = 0; i < 4; ++i) {
#pragma unroll
        for (int h = 0; h < 2; ++h) {
            const int gm = m0 + wm * 64 + i * 16 + g + h * 8;
            __half* rowp = g_h + (size_t)gm * I_DIM;
#pragma unroll
            for (int j = 0; j < 4; ++j) {
                const int base16 = n0 + wn * 32 + (j >> 1) * 16;
                const int off = 4 * c + 2 * (j & 1);
                float u0 = acc_u[i][j][h * 2 + 0], u1 = acc_u[i][j][h * 2 + 1];
                float gg0 = acc_g[i][j][h * 2 + 0], gg1 = acc_g[i][j][h * 2 + 1];
                float h0 = u0 * (gg0 / (1.f + __expf(-gg0)));
                float h1 = u1 * (gg1 / (1.f + __expf(-gg1)));
                *(__half2*)(rowp + base16 + off) = __floats2half2_rn(h0, h1);
            }
        }
    }
}

// ---------------------------------------------------------------------------
// Down GEMM. Block 256x128, 8 warps @ 64x64 (4m x 2n). A = g_h, B = g_wd.
// Scatter fp32 rows to out via g_idx.
// ---------------------------------------------------------------------------
#define STG_D (TILE256 + TILE128)

__global__ __launch_bounds__(NTHREADS, 1)
void down_kernel(float* __restrict__ out)
{
    const int Mc = g_count;
    const int m0 = blockIdx.y * 256;
    if (m0 >= Mc) return;
    const int n0 = blockIdx.x * 128;

    extern __shared__ __half smh[];

    const int tid  = threadIdx.x;
    const int lane = tid & 31;
    const int wid  = tid >> 5;
    const int wm   = wid >> 1;      // 0..3
    const int wn   = wid & 1;       // 0..1
    const int g    = lane >> 2;
    const int c    = lane & 3;

    const int nk = I_DIM / BKH;     // 172

    const __half* srcA = g_h  + (size_t)m0 * I_DIM;
    const __half* srcB = g_wd + (size_t)n0 * I_DIM;

#define ISSUE_D(t) do {                                                        \
        __half* st = smh + ((t) % S) * STG_D;                                   \
        const size_t kof = (size_t)(t) * BKH;                                  \
        _Pragma("unroll")                                                      \
        for (int ii = 0; ii < 8; ++ii) {                                       \
            int id = tid + ii * 256;                                           \
            int row = id >> 3, ch = id & 7;                                    \
            cp16(st + row * LDSTR + ch * 8,                                    \
                 srcA + (size_t)row * I_DIM + kof + ch * 8);                   \
        }                                                                      \
        _Pragma("unroll")                                                      \
        for (int ii = 0; ii < 4; ++ii) {                                       \
            int id = tid + ii * 256;                                           \
            int row = id >> 3, ch = id & 7;                                    \
            cp16(st + TILE256 + row * LDSTR + ch * 8,                          \
                 srcB + (size_t)row * I_DIM + kof + ch * 8);                   \
        }                                                                      \
    } while (0)

#pragma unroll
    for (int t = 0; t < S - 1; ++t) { ISSUE_D(t); CP_COMMIT(); }

    float acc[4][8][4];
#pragma unroll
    for (int i = 0; i < 4; ++i)
#pragma unroll
        for (int j = 0; j < 8; ++j)
#pragma unroll
            for (int r = 0; r < 4; ++r) acc[i][j][r] = 0.f;

    uint32_t af[2][4][4], bf[2][8][2];
    const int rbase = wm * 64 + g;
    const int nbase = wn * 64 + g;

    for (int t = 0; t < nk; ++t) {
        CP_WAIT(S - 2);
        __syncthreads();
        if (t + S - 1 < nk) ISSUE_D(t + S - 1);
        CP_COMMIT();

        const __half* As = smh + (t % S) * STG_D;
        const __half* Bs = As + TILE256;

        load_afrag(As, rbase, 0, c, af[0]);
        load_bfrag<8>(Bs, nbase, 0, c, bf[0]);

#pragma unroll
        for (int kg = 0; kg < 4; ++kg) {
            const int cur = kg & 1;
            if (kg < 3) {
                load_afrag(As, rbase, kg + 1, c, af[cur ^ 1]);
                load_bfrag<8>(Bs, nbase, kg + 1, c, bf[cur ^ 1]);
            }
#pragma unroll
            for (int i = 0; i < 4; ++i)
#pragma unroll
                for (int j = 0; j < 8; ++j)
                    mma16(acc[i][j], af[cur][i], bf[cur][j]);
        }
    }
#undef ISSUE_D

    // epilogue: scatter (natural fp32 layout)
#pragma unroll
    for (int i = 0; i < 4; ++i) {
#pragma unroll
        for (int h = 0; h < 2; ++h) {
            const int gm = m0 + wm * 64 + i * 16 + g + h * 8;
            if (gm < Mc) {
                float* rowp = out + (size_t)g_idx[gm] * H_DIM;
#pragma unroll
                for (int j = 0; j < 8; ++j) {
                    const int gn = n0 + wn * 64 + j * 8 + c * 2;
                    *(float2*)(rowp + gn) =
                        make_float2(acc[i][j][h * 2 + 0], acc[i][j][h * 2 + 1]);
                }
            }
        }
    }
}

// ---------------------------------------------------------------------------
extern "C" void kernel_launch(void* const* d_in, const int* in_sizes, int n_in,
                              void* d_out, int out_size)
{
    const float* hidden = (const float*)d_in[0];
    const float* w_up   = (const float*)d_in[1];
    const float* w_gate = (const float*)d_in[2];
    const float* w_down = (const float*)d_in[3];
    const int*   mask   = (const int*)d_in[4];
    float* out = (float*)d_out;

    const int SMEM_F = S * STG_F * sizeof(__half);   // 184320
    const int SMEM_D = S * STG_D * sizeof(__half);   // 184320
    cudaFuncSetAttribute(fused_upgate_kernel, cudaFuncAttributeMaxDynamicSharedMemorySize, SMEM_F);
    cudaFuncSetAttribute(down_kernel,         cudaFuncAttributeMaxDynamicSharedMemorySize, SMEM_D);

    void *d_wu, *d_wg, *d_wd;
    cudaGetSymbolAddress(&d_wu, g_wu);
    cudaGetSymbolAddress(&d_wg, g_wg);
    cudaGetSymbolAddress(&d_wd, g_wd);

    compact_kernel<<<1, 1024>>>(mask);
    gather_kernel<<<NTOK, 256>>>((const float4*)hidden);

    const int wg_groups = (I_DIM * H_DIM) / 16;   // 2,818,048
    cvt_permute_kernel<<<4096, 256>>>((const float4*)w_up,   (uint4*)d_wu, wg_groups);
    cvt_permute_kernel<<<4096, 256>>>((const float4*)w_gate, (uint4*)d_wg, wg_groups);
    cvt_permute_kernel<<<4096, 256>>>((const float4*)w_down, (uint4*)d_wd, wg_groups);

    const int n4 = (NTOK * H_DIM) / 4;
    zero_out_kernel<<<(n4 + 255) / 256, 256>>>((float4*)out, n4);

    dim3 blk(NTHREADS);
    fused_upgate_kernel<<<dim3(I_DIM / 128, NTOK / 128), blk, SMEM_F>>>();
    down_kernel<<<dim3(H_DIM / 128, NTOK / 256), blk, SMEM_D>>>(out);
}